// round 13
// baseline (speedup 1.0000x reference)
#include <cuda_runtime.h>
#include <cuda_fp16.h>
#include <cstdint>

// BahdanauAttention: B=64, S=2048, D=512, U=256
// score GEMM via mma.sync.m16n8k16 fp16 (A single fp16, B hi/lo split -> 2 MMAs).

#define NB 64
#define NS 2048
#define ND 512
#define NU 256
#define BS_TOT (NB * NS)

#define BM 128
#define BN 128
#define BK 32
#define NCH (ND / BK)          // 16 k-chunks
#define THREADS 512

#define LDAB 80                // bytes per smem row: 32 fp16 + 8 pad
#define ATILE (BM * LDAB)      // 10240 B
#define BTILE (BN * LDAB)      // 10240 B

// dynamic smem layout
#define oA   0                       // A hi only: [buf] -> 2 * ATILE
#define oB   (2 * ATILE)             // B: [prec][buf] -> 4 * BTILE
#define oPQ  (oB + 4 * BTILE)        // 128 floats
#define oV   (oPQ + 512)             // 128 floats
#define oRB  (oV + 512)              // row partials [128][4]
#define SMEM_BYTES (oRB + 2048)      // 64512

// ---------------- scratch (no allocations allowed) ----------------
__device__ __align__(16) float g_pq[NB * NU];
__device__ __align__(16) float g_sp[2][BS_TOT];        // score partials per u-half
__device__ __align__(16) float g_part[NB * 8 * ND];    // ctx partials
__device__ __align__(16) __half g_Whi[NU * ND];        // W1^T hi  [u][k]
__device__ __align__(16) __half g_Wlo[NU * ND];        // W1^T lo  [u][k]

// ---------------- helpers ----------------
__device__ __forceinline__ uint32_t smem_u32(const void* p) {
    uint32_t a;
    asm("{ .reg .u64 t; cvta.to.shared.u64 t, %1; cvt.u32.u64 %0, t; }" : "=r"(a) : "l"(p));
    return a;
}
__device__ __forceinline__ void ldsm_x4(uint32_t* r, uint32_t addr) {
    asm volatile("ldmatrix.sync.aligned.m8n8.x4.shared.b16 {%0,%1,%2,%3}, [%4];"
                 : "=r"(r[0]), "=r"(r[1]), "=r"(r[2]), "=r"(r[3]) : "r"(addr));
}
__device__ __forceinline__ void ldsm_x2(uint32_t* r, uint32_t addr) {
    asm volatile("ldmatrix.sync.aligned.m8n8.x2.shared.b16 {%0,%1}, [%2];"
                 : "=r"(r[0]), "=r"(r[1]) : "r"(addr));
}
__device__ __forceinline__ void mma16816(float* c, const uint32_t* a, const uint32_t* b) {
    asm volatile(
        "mma.sync.aligned.m16n8k16.row.col.f32.f16.f16.f32 "
        "{%0,%1,%2,%3}, {%4,%5,%6,%7}, {%8,%9}, {%0,%1,%2,%3};"
        : "+f"(c[0]), "+f"(c[1]), "+f"(c[2]), "+f"(c[3])
        : "r"(a[0]), "r"(a[1]), "r"(a[2]), "r"(a[3]), "r"(b[0]), "r"(b[1]));
}
__device__ __forceinline__ void cp_async16(uint32_t dst, const void* src) {
    asm volatile("cp.async.cg.shared.global [%0], [%1], 16;" :: "r"(dst), "l"(src));
}
#define CP_COMMIT() asm volatile("cp.async.commit_group;" ::: "memory")
#define CP_WAIT0()  asm volatile("cp.async.wait_group 0;" ::: "memory")

// convert 8 fp32 -> 8 fp16 packed in uint4
__device__ __forceinline__ uint4 cvt8(float4 v0, float4 v1) {
    __half2 h[4];
    h[0] = __float22half2_rn(make_float2(v0.x, v0.y));
    h[1] = __float22half2_rn(make_float2(v0.z, v0.w));
    h[2] = __float22half2_rn(make_float2(v1.x, v1.y));
    h[3] = __float22half2_rn(make_float2(v1.z, v1.w));
    return *(uint4*)h;
}

// ---------------------------------------------------------------------------
// prep: W1 [D,U] fp32 -> g_Whi/g_Wlo [U,D] fp16 hi/lo (transposed, K-contig)
// ---------------------------------------------------------------------------
__global__ void prep_w_kernel(const float* __restrict__ W1) {
    int u = blockIdx.x;
    for (int k = threadIdx.x; k < ND; k += blockDim.x) {
        float x = W1[(size_t)k * NU + u];
        __half h = __float2half(x);
        g_Whi[u * ND + k] = h;
        g_Wlo[u * ND + k] = __float2half(x - __half2float(h));
    }
}

// ---------------------------------------------------------------------------
// pq[b,u] = query[b,:]@W2[:,u] + b2[u] + b1[u]
// ---------------------------------------------------------------------------
__global__ void pq_kernel(const float* __restrict__ query,
                          const float* __restrict__ W2,
                          const float* __restrict__ b2,
                          const float* __restrict__ b1) {
    __shared__ float q[ND];
    int b = blockIdx.x;
    for (int i = threadIdx.x; i < ND; i += blockDim.x) q[i] = query[b * ND + i];
    __syncthreads();
    int u = threadIdx.x;
    float acc = b2[u] + b1[u];
#pragma unroll 8
    for (int d = 0; d < ND; d++) acc += q[d] * W2[d * NU + u];
    g_pq[b * NU + u] = acc;
}

// ---------------------------------------------------------------------------
// score kernel: HMMA fp16 GEMM (A single, B split -> 2 MMAs), CTA 128x128,
// 16 warps (4Mx4N), warp tile 32x32.  grid = (B*S/128)*2.
// ---------------------------------------------------------------------------
__global__ __launch_bounds__(THREADS, 1) void score_mma_kernel(
    const float* __restrict__ values, const float* __restrict__ Vvec,
    float* __restrict__ dummy) {
    extern __shared__ char sm[];
    uint32_t smA = smem_u32(sm);

    int tid = threadIdx.x;
    int wid = tid >> 5, lane = tid & 31;
    int wm = wid & 3, wn = wid >> 2;          // warp grid 4 (M) x 4 (N)
    int l16 = lane & 15;

    int rb = blockIdx.x >> 1;                 // row block
    int nh = blockIdx.x & 1;                  // u half
    int rowBase = rb * BM;
    int b = rowBase / NS;
    int uBase = nh * BN;

    // stage pq (this batch, this u-half) and V
    if (tid < BN) {
        ((float*)(sm + oPQ))[tid] = g_pq[b * NU + uBase + tid];
        ((float*)(sm + oV))[tid] = Vvec[uBase + tid];
    }

    // ldmatrix per-lane base addresses
    uint32_t aLdm = smA + oA + (uint32_t)(wm * 32 + l16) * LDAB + ((lane >> 4) * 16);
    uint32_t bLdm = smA + oB + (uint32_t)(wn * 32 + (l16 & 7)) * LDAB + ((l16 >> 3) * 16);

    // A global: thread -> row tid/4, k-quarter tid&3 (8 floats per chunk)
    int arow = tid >> 2, aq = tid & 3;
    const float* Ab = values + (size_t)(rowBase + arow) * ND + aq * 8;
    uint32_t aStOff = (uint32_t)arow * LDAB + aq * 16;

    float acc[2][4][4];
#pragma unroll
    for (int mt = 0; mt < 2; mt++)
#pragma unroll
        for (int nt = 0; nt < 4; nt++)
#pragma unroll
            for (int i = 0; i < 4; i++) acc[mt][nt][i] = 0.f;

    // ---- B stage via cp.async (hi+lo), 2 x 16B per thread per chunk ----
    auto stageB = [&](int kc, int buf) {
        int u = tid >> 2, seg = tid & 3;
        size_t ge = (size_t)(uBase + u) * ND + kc * BK + seg * 8;
        uint32_t d = smA + oB + (uint32_t)buf * BTILE + (uint32_t)u * LDAB + seg * 16;
        cp_async16(d, g_Whi + ge);
        cp_async16(d + 2 * BTILE, g_Wlo + ge);
    };

    // ---- prologue: stage chunk 0 ----
    {
        float4 v0 = *(const float4*)(Ab + 0), v1 = *(const float4*)(Ab + 4);
        *(uint4*)(sm + oA + aStOff) = cvt8(v0, v1);
        stageB(0, 0);
        CP_COMMIT();
    }

    for (int kc = 0; kc < NCH; kc++) {
        CP_WAIT0();
        __syncthreads();
        int buf = kc & 1;

        // prefetch next chunk: A -> regs (8 floats), B -> cp.async
        float4 p0, p1;
        if (kc + 1 < NCH) {
            const float* gA = Ab + (kc + 1) * BK;
            p0 = *(const float4*)(gA + 0);
            p1 = *(const float4*)(gA + 4);
            stageB(kc + 1, buf ^ 1);
            CP_COMMIT();
        }

        // ---- compute: 2 k-steps of 16 ----
#pragma unroll
        for (int ks = 0; ks < 2; ks++) {
            uint32_t ah[2][4], bf[4][2];
#pragma unroll
            for (int mt = 0; mt < 2; mt++)
                ldsm_x4(ah[mt], aLdm + (uint32_t)buf * ATILE + mt * 16 * LDAB + ks * 32);
#pragma unroll
            for (int nt = 0; nt < 4; nt++)
                ldsm_x2(bf[nt], bLdm + (uint32_t)buf * BTILE + nt * 8 * LDAB + ks * 32);
#pragma unroll
            for (int mt = 0; mt < 2; mt++)
#pragma unroll
                for (int nt = 0; nt < 4; nt++)
                    mma16816(acc[mt][nt], ah[mt], bf[nt]);   // a*hi
#pragma unroll
            for (int nt = 0; nt < 4; nt++)
                ldsm_x2(bf[nt], bLdm + 2 * BTILE + (uint32_t)buf * BTILE + nt * 8 * LDAB + ks * 32);
#pragma unroll
            for (int mt = 0; mt < 2; mt++)
#pragma unroll
                for (int nt = 0; nt < 4; nt++)
                    mma16816(acc[mt][nt], ah[mt], bf[nt]);   // a*lo
        }

        // store prefetched A into the other buffer
        if (kc + 1 < NCH)
            *(uint4*)(sm + oA + (buf ^ 1) * ATILE + aStOff) = cvt8(p0, p1);
    }

    // ---- epilogue: tanh(pv+pq)*V, row-sum over this CTA's 128 u ----
    const float* pqs = (const float*)(sm + oPQ);
    const float* vs = (const float*)(sm + oV);
    float rs[4] = {0.f, 0.f, 0.f, 0.f};   // [mt][rowhalf]
#pragma unroll
    for (int mt = 0; mt < 2; mt++)
#pragma unroll
        for (int nt = 0; nt < 4; nt++) {
            int ul = wn * 32 + nt * 8 + (lane & 3) * 2;
            float p0 = pqs[ul], p1 = pqs[ul + 1];
            float v0 = vs[ul], v1 = vs[ul + 1];
            rs[mt * 2 + 0] += tanhf(acc[mt][nt][0] + p0) * v0 + tanhf(acc[mt][nt][1] + p1) * v1;
            rs[mt * 2 + 1] += tanhf(acc[mt][nt][2] + p0) * v0 + tanhf(acc[mt][nt][3] + p1) * v1;
        }
#pragma unroll
    for (int i = 0; i < 4; i++) {
        rs[i] += __shfl_xor_sync(0xffffffffu, rs[i], 1);
        rs[i] += __shfl_xor_sync(0xffffffffu, rs[i], 2);
    }
    float* rbuf = (float*)(sm + oRB);
    if ((lane & 3) == 0) {
#pragma unroll
        for (int mt = 0; mt < 2; mt++)
#pragma unroll
            for (int h = 0; h < 2; h++) {
                int r = wm * 32 + mt * 16 + h * 8 + (lane >> 2);
                rbuf[r * 4 + wn] = rs[mt * 2 + h];
            }
    }
    __syncthreads();
    if (tid < BM)
        g_sp[nh][rowBase + tid] =
            (rbuf[tid * 4] + rbuf[tid * 4 + 1]) + (rbuf[tid * 4 + 2] + rbuf[tid * 4 + 3]);
}

// ---------------------------------------------------------------------------
// softmax over S per batch; merges the two u-half score partials.
// ---------------------------------------------------------------------------
__global__ void softmax_kernel(float* __restrict__ attn) {
    __shared__ float red[256];
    int b = blockIdx.x, tid = threadIdx.x;
    size_t base = (size_t)b * NS;
    float v[8];
    float m = -1e30f;
#pragma unroll
    for (int j = 0; j < 8; j++) {
        size_t i = base + tid + j * 256;
        v[j] = g_sp[0][i] + g_sp[1][i];
        m = fmaxf(m, v[j]);
    }
    red[tid] = m;
    __syncthreads();
    for (int o = 128; o > 0; o >>= 1) {
        if (tid < o) red[tid] = fmaxf(red[tid], red[tid + o]);
        __syncthreads();
    }
    m = red[0];
    __syncthreads();
    float s = 0.f;
#pragma unroll
    for (int j = 0; j < 8; j++) {
        v[j] = __expf(v[j] - m);
        s += v[j];
    }
    red[tid] = s;
    __syncthreads();
    for (int o = 128; o > 0; o >>= 1) {
        if (tid < o) red[tid] += red[tid + o];
        __syncthreads();
    }
    float inv = 1.f / red[0];
#pragma unroll
    for (int j = 0; j < 8; j++) attn[base + tid + j * 256] = v[j] * inv;
}

// ---------------------------------------------------------------------------
// context partials + reduce (deterministic, no atomics)
// ---------------------------------------------------------------------------
__global__ __launch_bounds__(128) void ctx_part_kernel(
    const float* __restrict__ values, const float* __restrict__ attn) {
    __shared__ float a[256];
    int blk = blockIdx.x;
    int b = blk >> 5;
    int sc = (blk >> 2) & 7;
    int dc = blk & 3;
    int tid = threadIdx.x;
    a[tid] = attn[(size_t)b * NS + sc * 256 + tid];
    a[tid + 128] = attn[(size_t)b * NS + sc * 256 + tid + 128];
    __syncthreads();
    int d = dc * 128 + tid;
    const float* vp = values + ((size_t)b * NS + (size_t)sc * 256) * ND + d;
    float acc = 0.f;
#pragma unroll 8
    for (int s = 0; s < 256; s++) acc += a[s] * vp[(size_t)s * ND];
    g_part[((size_t)b * 8 + sc) * ND + d] = acc;
}

__global__ void ctx_reduce_kernel(float* __restrict__ ctx) {
    int idx = blockIdx.x * 256 + threadIdx.x;
    int b = idx >> 9, d = idx & 511;
    float s = 0.f;
#pragma unroll
    for (int sc = 0; sc < 8; sc++) s += g_part[((size_t)b * 8 + sc) * ND + d];
    ctx[idx] = s;
}

// ---------------------------------------------------------------------------
extern "C" void kernel_launch(void* const* d_in, const int* in_sizes, int n_in,
                              void* d_out, int out_size) {
    const float* query = (const float*)d_in[0];
    const float* values = (const float*)d_in[1];
    const float* W1 = (const float*)d_in[2];
    const float* b1 = (const float*)d_in[3];
    const float* W2 = (const float*)d_in[4];
    const float* b2 = (const float*)d_in[5];
    const float* V = (const float*)d_in[6];
    // d_in[7] = bV: cancels in softmax

    float* ctx = (float*)d_out;            // [B*D]
    float* attn = (float*)d_out + NB * ND; // [B*S]

    cudaFuncSetAttribute(score_mma_kernel,
                         cudaFuncAttributeMaxDynamicSharedMemorySize, SMEM_BYTES);

    prep_w_kernel<<<NU, 128>>>(W1);
    pq_kernel<<<NB, 256>>>(query, W2, b2, b1);
    score_mma_kernel<<<(BS_TOT / BM) * 2, THREADS, SMEM_BYTES>>>(values, V, attn);
    softmax_kernel<<<NB, 256>>>(attn);
    ctx_part_kernel<<<NB * 8 * 4, 128>>>(values, attn);
    ctx_reduce_kernel<<<(NB * ND) / 256, 256>>>(ctx);
}